// round 1
// baseline (speedup 1.0000x reference)
#include <cuda_runtime.h>
#include <math.h>

#define Bb 4
#define Ss 512
#define Hh 768
#define Dd 24
#define Mm 96
#define OH 768
#define H3 2304
#define NROWS (Bb*Ss)   // 2048

// ---- scratch (statically allocated; no runtime allocation) ----
__device__ float g_Zj[NROWS*Dd];
__device__ float g_Zi[NROWS*Dd];
__device__ float g_Aj[NROWS*Mm];
__device__ float g_Bi[NROWS*Mm];
__device__ float g_probs[(long)Bb*Ss*Ss];
__device__ float g_ctx[(long)NROWS*Hh];
__device__ float g_msgin[(long)NROWS*H3];
__device__ float g_hid2[(long)NROWS*OH];

// ---- packed f32x2 helpers (FFMA2: ptxas won't auto-fuse; PTX only) ----
__device__ __forceinline__ unsigned long long pack2(float lo, float hi){
    unsigned long long r;
    asm("mov.b64 %0, {%1, %2};" : "=l"(r) : "f"(lo), "f"(hi));
    return r;
}
__device__ __forceinline__ void unpack2(unsigned long long v, float& lo, float& hi){
    asm("mov.b64 {%0, %1}, %2;" : "=f"(lo), "=f"(hi) : "l"(v));
}
__device__ __forceinline__ unsigned long long fma2(unsigned long long a,
                                                   unsigned long long b,
                                                   unsigned long long c){
    unsigned long long d;
    asm("fma.rn.f32x2 %0, %1, %2, %3;" : "=l"(d) : "l"(a), "l"(b), "l"(c));
    return d;
}

// ============================================================
// K1: Zj = H_j @ p_j_w^T, Zi = H_i @ p_i_w^T  (per-row),
//     Aj = Wa @ zj, Bi = Wb @ zi  (rank-1 softmax-MLP terms)
// one block per (b,s) row
// ============================================================
__global__ __launch_bounds__(256) void proj_kernel(
    const float* __restrict__ Hj, const float* __restrict__ Hi,
    const float* __restrict__ pjw, const float* __restrict__ piw,
    const float* __restrict__ sw1)
{
    int r = blockIdx.x;
    __shared__ float shj[Hh], shi[Hh], szj[Dd], szi[Dd];
    int tid = threadIdx.x;
    for (int i = tid; i < Hh; i += 256){
        shj[i] = Hj[(long)r*Hh + i];
        shi[i] = Hi[(long)r*Hh + i];
    }
    __syncthreads();
    int o = tid >> 3, g = tid & 7;     // 8 threads per output d
    if (o < Dd){
        float pj = 0.f, pi = 0.f;
        for (int h = g; h < Hh; h += 8){
            pj += shj[h] * pjw[o*Hh + h];
            pi += shi[h] * piw[o*Hh + h];
        }
        #pragma unroll
        for (int d = 4; d > 0; d >>= 1){
            pj += __shfl_down_sync(0xffffffffu, pj, d, 8);
            pi += __shfl_down_sync(0xffffffffu, pi, d, 8);
        }
        if (g == 0){
            szj[o] = pj; szi[o] = pi;
            g_Zj[r*Dd + o] = pj; g_Zi[r*Dd + o] = pi;
        }
    }
    __syncthreads();
    if (tid < Mm){
        float a = 0.f, bsum = 0.f;
        #pragma unroll
        for (int d = 0; d < Dd; d++){
            a    += sw1[tid*96 +      d] * szj[d];   // Wa
            bsum += sw1[tid*96 + 24 + d] * szi[d];   // Wb
        }
        g_Aj[r*Mm + tid] = a;
        g_Bi[r*Mm + tid] = bsum;
    }
}

// ============================================================
// K2: pairwise logits + masked softmax -> probs
// one block per (b,s); each thread handles t=tid and t=tid+256
// ============================================================
__global__ __launch_bounds__(256) void pair_kernel(
    const float* __restrict__ sw1, const float* __restrict__ sb1,
    const float* __restrict__ sw2v, const float* __restrict__ sb2,
    const float* __restrict__ mask)
{
    int r = blockIdx.x;
    int b = r / Ss;
    __shared__ float sWc[Mm*Dd], sWd[Mm*Dd], sw2[Mm], sc[Mm], szj[Dd];
    __shared__ float sred[8];
    int tid = threadIdx.x;

    for (int i = tid; i < Mm*Dd; i += 256){
        int m = i / Dd, d = i % Dd;
        sWc[i] = sw1[m*96 + 48 + d];   // Wc
        sWd[i] = sw1[m*96 + 72 + d];   // Wd
    }
    if (tid < Mm){
        sw2[tid] = sw2v[tid];
        sc[tid]  = g_Aj[r*Mm + tid] + sb1[tid];
    }
    if (tid < Dd) szj[tid] = g_Zj[r*Dd + tid];
    __syncthreads();

    float lt[2];
    #pragma unroll
    for (int tt = 0; tt < 2; ++tt){
        int t = tid + tt*256;
        const float* zi = &g_Zi[(long)(b*Ss + t)*Dd];
        float u[Dd], v[Dd];
        #pragma unroll
        for (int d = 0; d < Dd; d++){
            float z = __ldg(&zi[d]);
            u[d] = szj[d] * z;
            v[d] = fabsf(szj[d] - z);
        }
        const float4* bi4 = (const float4*)&g_Bi[(long)(b*Ss + t)*Mm];
        float logit = 0.f;
        #pragma unroll 2
        for (int m4 = 0; m4 < Mm/4; m4++){
            float4 bv = __ldg(&bi4[m4]);
            float bb[4] = {bv.x, bv.y, bv.z, bv.w};
            #pragma unroll
            for (int j = 0; j < 4; j++){
                int m = m4*4 + j;
                float h = sc[m] + bb[j];
                const float* wc = &sWc[m*Dd];
                const float* wd = &sWd[m*Dd];
                #pragma unroll
                for (int d = 0; d < Dd; d++)
                    h += wc[d]*u[d] + wd[d]*v[d];
                logit += sw2[m] * fmaxf(h, 0.f);
            }
        }
        lt[tt] = logit + sb2[0]
               + (1.f - mask[b*Ss + t]) * (-3.402823466e38f);
    }

    // block softmax over 512 logits (2 per thread)
    float mx = fmaxf(lt[0], lt[1]);
    #pragma unroll
    for (int d = 16; d > 0; d >>= 1)
        mx = fmaxf(mx, __shfl_xor_sync(0xffffffffu, mx, d));
    if ((tid & 31) == 0) sred[tid >> 5] = mx;
    __syncthreads();
    float bmax = sred[0];
    #pragma unroll
    for (int i = 1; i < 8; i++) bmax = fmaxf(bmax, sred[i]);

    float e0 = expf(lt[0] - bmax);
    float e1 = expf(lt[1] - bmax);
    float sm = e0 + e1;
    #pragma unroll
    for (int d = 16; d > 0; d >>= 1)
        sm += __shfl_xor_sync(0xffffffffu, sm, d);
    __syncthreads();                 // protect sred reuse
    if ((tid & 31) == 0) sred[tid >> 5] = sm;
    __syncthreads();
    float tot = 0.f;
    #pragma unroll
    for (int i = 0; i < 8; i++) tot += sred[i];
    float inv = 1.f / tot;

    g_probs[(long)r*Ss + tid      ] = e0 * inv;
    g_probs[(long)r*Ss + tid + 256] = e1 * inv;
}

// ============================================================
// K3/K5/K6: tiled SGEMM, 64x64 tile, 16 k-slice, 4x4/thread,
//           f32x2 packed accumulation (FFMA2)
// C(MxN) = scale * (act(A @ opB + bias))
// TRANSB=false: B is KxN row-major.  TRANSB=true: B is NxK row-major.
// ============================================================
template<bool TRANSB, bool RELU>
__global__ __launch_bounds__(256) void gemm_kernel(
    const float* __restrict__ A, const float* __restrict__ Bm,
    float* __restrict__ C, int N, int K,
    long strideA, long strideB, long strideC,
    const float* __restrict__ bias, const float* __restrict__ scale_ptr)
{
    A  += (long)blockIdx.z * strideA;
    Bm += (long)blockIdx.z * strideB;
    C  += (long)blockIdx.z * strideC;

    __shared__ float As[16][68];
    __shared__ float Bs[16][68];
    int tid = threadIdx.x;
    int tx = tid & 15, ty = tid >> 4;
    int row0 = blockIdx.y * 64, col0 = blockIdx.x * 64;

    unsigned long long acc[4][2];
    #pragma unroll
    for (int i = 0; i < 4; i++){ acc[i][0] = 0ull; acc[i][1] = 0ull; }

    int a_r = tid >> 2;            // 0..63
    int a_k = (tid & 3) * 4;       // 0,4,8,12
    int bn_k = tid >> 4;           // NN path: 0..15
    int bn_c = (tid & 15) * 4;

    for (int kt = 0; kt < K; kt += 16){
        float4 av = *(const float4*)&A[(long)(row0 + a_r)*K + kt + a_k];
        As[a_k+0][a_r] = av.x; As[a_k+1][a_r] = av.y;
        As[a_k+2][a_r] = av.z; As[a_k+3][a_r] = av.w;
        if (TRANSB){
            float4 bv = *(const float4*)&Bm[(long)(col0 + a_r)*K + kt + a_k];
            Bs[a_k+0][a_r] = bv.x; Bs[a_k+1][a_r] = bv.y;
            Bs[a_k+2][a_r] = bv.z; Bs[a_k+3][a_r] = bv.w;
        } else {
            float4 bv = *(const float4*)&Bm[(long)(kt + bn_k)*N + col0 + bn_c];
            *(float4*)&Bs[bn_k][bn_c] = bv;
        }
        __syncthreads();
        #pragma unroll
        for (int k = 0; k < 16; k++){
            float4 a  = *(const float4*)&As[k][ty*4];
            float4 bq = *(const float4*)&Bs[k][tx*4];
            unsigned long long b01 = pack2(bq.x, bq.y);
            unsigned long long b23 = pack2(bq.z, bq.w);
            float aa[4] = {a.x, a.y, a.z, a.w};
            #pragma unroll
            for (int i = 0; i < 4; i++){
                unsigned long long ai = pack2(aa[i], aa[i]);
                acc[i][0] = fma2(ai, b01, acc[i][0]);
                acc[i][1] = fma2(ai, b23, acc[i][1]);
            }
        }
        __syncthreads();
    }

    float sc = scale_ptr ? __ldg(scale_ptr) : 1.f;
    #pragma unroll
    for (int i = 0; i < 4; i++){
        int row = row0 + ty*4 + i;
        float c0,c1,c2,c3;
        unpack2(acc[i][0], c0, c1);
        unpack2(acc[i][1], c2, c3);
        float cv[4] = {c0,c1,c2,c3};
        #pragma unroll
        for (int j = 0; j < 4; j++){
            int col = col0 + tx*4 + j;
            float v = cv[j];
            if (bias) v += bias[col];
            if (RELU) v = fmaxf(v, 0.f);
            v *= sc;
            C[(long)row*N + col] = v;
        }
    }
}

// ============================================================
// K4: msg_in = concat([ctx, H_j, ctx*H_j], -1)
// ============================================================
__global__ __launch_bounds__(256) void msgin_kernel(const float* __restrict__ Hj)
{
    long idx = (long)blockIdx.x * 256 + threadIdx.x;
    if (idx >= (long)NROWS * H3) return;
    int r = (int)(idx / H3);
    int c = (int)(idx % H3);
    float v;
    if (c < Hh)          v = g_ctx[(long)r*Hh + c];
    else if (c < 2*Hh)   v = Hj[(long)r*Hh + (c - Hh)];
    else {
        int cc = c - 2*Hh;
        v = g_ctx[(long)r*Hh + cc] * Hj[(long)r*Hh + cc];
    }
    g_msgin[idx] = v;
}

// ============================================================
extern "C" void kernel_launch(void* const* d_in, const int* in_sizes, int n_in,
                              void* d_out, int out_size)
{
    const float* Hj   = (const float*)d_in[0];
    const float* Hi   = (const float*)d_in[1];
    const float* mask = (const float*)d_in[2];
    const float* pjw  = (const float*)d_in[3];
    const float* piw  = (const float*)d_in[4];
    const float* sw1  = (const float*)d_in[5];
    const float* sb1  = (const float*)d_in[6];
    const float* sw2  = (const float*)d_in[7];
    const float* sb2  = (const float*)d_in[8];
    const float* vw1  = (const float*)d_in[9];
    const float* vb1  = (const float*)d_in[10];
    const float* vw2  = (const float*)d_in[11];
    const float* vb2  = (const float*)d_in[12];
    const float* alpha= (const float*)d_in[13];
    float* out = (float*)d_out;

    void *pprobs, *pctx, *pmsg, *phid;
    cudaGetSymbolAddress(&pprobs, g_probs);
    cudaGetSymbolAddress(&pctx,   g_ctx);
    cudaGetSymbolAddress(&pmsg,   g_msgin);
    cudaGetSymbolAddress(&phid,   g_hid2);

    proj_kernel<<<NROWS, 256>>>(Hj, Hi, pjw, piw, sw1);
    pair_kernel<<<NROWS, 256>>>(sw1, sb1, sw2, sb2, mask);

    // ctx_b = probs_b (SxS) @ Hi_b (SxH)   [NN, batched over b]
    {
        dim3 g(Hh/64, Ss/64, Bb);
        gemm_kernel<false,false><<<g, 256>>>(
            (const float*)pprobs, Hi, (float*)pctx, Hh, Ss,
            (long)Ss*Ss, (long)Ss*Hh, (long)Ss*Hh, nullptr, nullptr);
    }

    msgin_kernel<<<(int)(((long)NROWS*H3 + 255)/256), 256>>>(Hj);

    // hid2 = relu(msg_in @ v_w1^T + v_b1)   [NT]
    {
        dim3 g(OH/64, NROWS/64, 1);
        gemm_kernel<true,true><<<g, 256>>>(
            (const float*)pmsg, vw1, (float*)phid, OH, H3,
            0, 0, 0, vb1, nullptr);
    }

    // out = alpha * (hid2 @ v_w2^T + v_b2)  [NT]
    {
        dim3 g(Hh/64, NROWS/64, 1);
        gemm_kernel<true,false><<<g, 256>>>(
            (const float*)phid, vw2, out, Hh, OH,
            0, 0, 0, vb2, alpha);
    }
    (void)in_sizes; (void)n_in; (void)out_size;
}

// round 2
// speedup vs baseline: 1.0726x; 1.0726x over previous
#include <cuda_runtime.h>
#include <math.h>

#define Bb 4
#define Ss 512
#define Hh 768
#define Dd 24
#define Mm 96
#define OH 768
#define H3 2304
#define NROWS (Bb*Ss)   // 2048

typedef unsigned long long ull;

// ---- scratch (statically allocated; no runtime allocation) ----
__device__ float g_Zj[NROWS*Dd];
__device__ float g_Zi[NROWS*Dd];
__device__ float g_Aj[NROWS*Mm];
__device__ float g_Bi[NROWS*Mm];
__device__ float g_probs[(long)Bb*Ss*Ss];
__device__ float g_ctx[(long)NROWS*Hh];
__device__ float g_msgin[(long)NROWS*H3];
__device__ float g_hid2[(long)NROWS*OH];
__device__ float g_part1[2L*NROWS*OH];
__device__ float g_part2[2L*NROWS*Hh];

// ---- packed f32x2 helpers ----
__device__ __forceinline__ ull pack2(float lo, float hi){
    ull r; asm("mov.b64 %0, {%1, %2};" : "=l"(r) : "f"(lo), "f"(hi)); return r;
}
__device__ __forceinline__ void unpack2(ull v, float& lo, float& hi){
    asm("mov.b64 {%0, %1}, %2;" : "=f"(lo), "=f"(hi) : "l"(v));
}
__device__ __forceinline__ ull fma2(ull a, ull b, ull c){
    ull d; asm("fma.rn.f32x2 %0, %1, %2, %3;" : "=l"(d) : "l"(a), "l"(b), "l"(c));
    return d;
}

// ============================================================
// K1: projections + rank-1 softmax-MLP terms
// ============================================================
__global__ __launch_bounds__(256) void proj_kernel(
    const float* __restrict__ Hj, const float* __restrict__ Hi,
    const float* __restrict__ pjw, const float* __restrict__ piw,
    const float* __restrict__ sw1)
{
    int r = blockIdx.x;
    __shared__ float shj[Hh], shi[Hh], szj[Dd], szi[Dd];
    int tid = threadIdx.x;
    for (int i = tid; i < Hh; i += 256){
        shj[i] = Hj[(long)r*Hh + i];
        shi[i] = Hi[(long)r*Hh + i];
    }
    __syncthreads();
    int o = tid >> 3, g = tid & 7;
    if (o < Dd){
        float pj = 0.f, pi = 0.f;
        for (int h = g; h < Hh; h += 8){
            pj += shj[h] * pjw[o*Hh + h];
            pi += shi[h] * piw[o*Hh + h];
        }
        #pragma unroll
        for (int d = 4; d > 0; d >>= 1){
            pj += __shfl_down_sync(0xffffffffu, pj, d, 8);
            pi += __shfl_down_sync(0xffffffffu, pi, d, 8);
        }
        if (g == 0){
            szj[o] = pj; szi[o] = pi;
            g_Zj[r*Dd + o] = pj; g_Zi[r*Dd + o] = pi;
        }
    }
    __syncthreads();
    if (tid < Mm){
        float a = 0.f, bsum = 0.f;
        #pragma unroll
        for (int d = 0; d < Dd; d++){
            a    += sw1[tid*96 +      d] * szj[d];
            bsum += sw1[tid*96 + 24 + d] * szi[d];
        }
        g_Aj[r*Mm + tid] = a;
        g_Bi[r*Mm + tid] = bsum;
    }
}

// ============================================================
// K2: pairwise logits + masked softmax -> probs  (f32x2 version)
// weights packed (wc,wd) in SMEM, (u,v) packed in regs
// ============================================================
__global__ __launch_bounds__(256) void pair_kernel(
    const float* __restrict__ sw1, const float* __restrict__ sb1,
    const float* __restrict__ sw2v, const float* __restrict__ sb2,
    const float* __restrict__ mask)
{
    int r = blockIdx.x;
    int b = r / Ss;
    __shared__ float2 sWcd[Mm*Dd];        // (wc, wd) per (m,d)
    __shared__ float sw2[Mm], sc[Mm], szj[Dd];
    __shared__ float sred[8];
    int tid = threadIdx.x;

    for (int i = tid; i < Mm*Dd; i += 256){
        int m = i / Dd, d = i % Dd;
        sWcd[i] = make_float2(sw1[m*96 + 48 + d], sw1[m*96 + 72 + d]);
    }
    if (tid < Mm){
        sw2[tid] = sw2v[tid];
        sc[tid]  = g_Aj[r*Mm + tid] + sb1[tid];
    }
    if (tid < Dd) szj[tid] = g_Zj[r*Dd + tid];
    __syncthreads();

    int t0 = tid, t1 = tid + 256;
    const float* zi0 = &g_Zi[(long)(b*Ss + t0)*Dd];
    const float* zi1 = &g_Zi[(long)(b*Ss + t1)*Dd];
    ull uv0[Dd], uv1[Dd];
    #pragma unroll
    for (int d = 0; d < Dd; d++){
        float zj = szj[d];
        float z0 = __ldg(&zi0[d]);
        float z1 = __ldg(&zi1[d]);
        uv0[d] = pack2(zj*z0, fabsf(zj - z0));
        uv1[d] = pack2(zj*z1, fabsf(zj - z1));
    }

    const float4* bi0 = (const float4*)&g_Bi[(long)(b*Ss + t0)*Mm];
    const float4* bi1 = (const float4*)&g_Bi[(long)(b*Ss + t1)*Mm];
    float logit0 = 0.f, logit1 = 0.f;

    #pragma unroll 1
    for (int mg = 0; mg < Mm/4; mg++){
        float4 bv0 = __ldg(&bi0[mg]);
        float4 bv1 = __ldg(&bi1[mg]);
        float bb0[4] = {bv0.x, bv0.y, bv0.z, bv0.w};
        float bb1[4] = {bv1.x, bv1.y, bv1.z, bv1.w};
        #pragma unroll
        for (int j = 0; j < 4; j++){
            int m = mg*4 + j;
            const ull* w = (const ull*)&sWcd[m*Dd];
            ull h0 = 0ull, h1 = 0ull;
            #pragma unroll
            for (int d = 0; d < Dd; d++){
                ull wv = w[d];
                h0 = fma2(uv0[d], wv, h0);
                h1 = fma2(uv1[d], wv, h1);
            }
            float a0,c0,a1,c1;
            unpack2(h0, a0, c0);
            unpack2(h1, a1, c1);
            float base = sc[m];
            float hv0 = base + bb0[j] + a0 + c0;
            float hv1 = base + bb1[j] + a1 + c1;
            float w2 = sw2[m];
            logit0 += w2 * fmaxf(hv0, 0.f);
            logit1 += w2 * fmaxf(hv1, 0.f);
        }
    }
    float lt0 = logit0 + sb2[0] + (1.f - mask[b*Ss + t0]) * (-3.402823466e38f);
    float lt1 = logit1 + sb2[0] + (1.f - mask[b*Ss + t1]) * (-3.402823466e38f);

    // block softmax over 512 logits
    float mx = fmaxf(lt0, lt1);
    #pragma unroll
    for (int d = 16; d > 0; d >>= 1)
        mx = fmaxf(mx, __shfl_xor_sync(0xffffffffu, mx, d));
    if ((tid & 31) == 0) sred[tid >> 5] = mx;
    __syncthreads();
    float bmax = sred[0];
    #pragma unroll
    for (int i = 1; i < 8; i++) bmax = fmaxf(bmax, sred[i]);

    float e0 = expf(lt0 - bmax);
    float e1 = expf(lt1 - bmax);
    float sm = e0 + e1;
    #pragma unroll
    for (int d = 16; d > 0; d >>= 1)
        sm += __shfl_xor_sync(0xffffffffu, sm, d);
    __syncthreads();
    if ((tid & 31) == 0) sred[tid >> 5] = sm;
    __syncthreads();
    float tot = 0.f;
    #pragma unroll
    for (int i = 0; i < 8; i++) tot += sred[i];
    float inv = 1.f / tot;

    g_probs[(long)r*Ss + t0] = e0 * inv;
    g_probs[(long)r*Ss + t1] = e1 * inv;
}

// ============================================================
// K3: tiled SGEMM v2 — 128x128 tile, 8x8/thread, f32x2,
//     double-buffered SMEM. EPI: 0 = raw store (partial/ctx),
//     1 = bias+relu, 2 = bias+scale
// TRANSB=false: B is KxN row-major. TRANSB=true: B is NxK row-major.
// SPLITK: blockIdx.z selects k-range (and C partial slab).
// ============================================================
template<bool TRANSB, bool SPLITK, int EPI>
__global__ __launch_bounds__(256) void gemm2_kernel(
    const float* __restrict__ A, const float* __restrict__ Bm,
    float* __restrict__ C, int N, int ldA, int ldB, int kcnt,
    long strideA, long strideB, long strideC,
    const float* __restrict__ bias, const float* __restrict__ scale_ptr)
{
    __shared__ float As[2][8][132];
    __shared__ float Bs[2][8][132];
    int tid = threadIdx.x;
    A  += (long)blockIdx.z * strideA;
    Bm += (long)blockIdx.z * strideB;
    C  += (long)blockIdx.z * strideC;
    int k0 = SPLITK ? blockIdx.z * kcnt : 0;
    int row0 = blockIdx.y * 128, col0 = blockIdx.x * 128;
    int lr = tid >> 1, lk = (tid & 1) * 4;     // A / NT-B loaders
    int nk = tid >> 5, nc = (tid & 31) * 4;    // NN-B loaders
    int tx = tid & 15, ty = tid >> 4;

    const float* Aptr = A + (long)(row0 + lr)*ldA + k0 + lk;
    const float* Bptr = TRANSB ? (Bm + (long)(col0 + lr)*ldB + k0 + lk)
                               : (Bm + (long)(k0 + nk)*ldB + col0 + nc);

    float4 av = *(const float4*)Aptr;
    float4 bv = *(const float4*)Bptr;

    ull acc[8][4];
    #pragma unroll
    for (int i = 0; i < 8; i++)
        #pragma unroll
        for (int j = 0; j < 4; j++) acc[i][j] = 0ull;

    int nslices = kcnt >> 3;
    #pragma unroll 1
    for (int s = 0; s < nslices; s++){
        int cur = s & 1;
        // stage registers -> SMEM
        As[cur][lk+0][lr] = av.x; As[cur][lk+1][lr] = av.y;
        As[cur][lk+2][lr] = av.z; As[cur][lk+3][lr] = av.w;
        if (TRANSB){
            Bs[cur][lk+0][lr] = bv.x; Bs[cur][lk+1][lr] = bv.y;
            Bs[cur][lk+2][lr] = bv.z; Bs[cur][lk+3][lr] = bv.w;
        } else {
            *(float4*)&Bs[cur][nk][nc] = bv;
        }
        __syncthreads();
        if (s + 1 < nslices){
            Aptr += 8;
            av = *(const float4*)Aptr;
            if (TRANSB){ Bptr += 8; }
            else       { Bptr += 8L * ldB; }
            bv = *(const float4*)Bptr;
        }
        #pragma unroll
        for (int k = 0; k < 8; k++){
            float4 a0 = *(const float4*)&As[cur][k][ty*8];
            float4 a1 = *(const float4*)&As[cur][k][ty*8 + 4];
            float4 b0 = *(const float4*)&Bs[cur][k][tx*8];
            float4 b1 = *(const float4*)&Bs[cur][k][tx*8 + 4];
            ull bp[4] = {pack2(b0.x,b0.y), pack2(b0.z,b0.w),
                         pack2(b1.x,b1.y), pack2(b1.z,b1.w)};
            float aa[8] = {a0.x,a0.y,a0.z,a0.w,a1.x,a1.y,a1.z,a1.w};
            #pragma unroll
            for (int i = 0; i < 8; i++){
                ull ai = pack2(aa[i], aa[i]);
                #pragma unroll
                for (int j = 0; j < 4; j++)
                    acc[i][j] = fma2(ai, bp[j], acc[i][j]);
            }
        }
        __syncthreads();
    }

    float sc = (EPI == 2) ? __ldg(scale_ptr) : 1.f;
    #pragma unroll
    for (int i = 0; i < 8; i++){
        int row = row0 + ty*8 + i;
        float cv[8];
        #pragma unroll
        for (int j = 0; j < 4; j++) unpack2(acc[i][j], cv[2*j], cv[2*j+1]);
        #pragma unroll
        for (int j = 0; j < 8; j++){
            int col = col0 + tx*8 + j;
            float v = cv[j];
            if (EPI >= 1) v += bias[col];
            if (EPI == 1) v = fmaxf(v, 0.f);
            if (EPI == 2) v *= sc;
            C[(long)row*N + col] = v;
        }
    }
}

// ============================================================
// K4: msg_in = concat([ctx, H_j, ctx*H_j], -1)
// ============================================================
__global__ __launch_bounds__(256) void msgin_kernel(const float* __restrict__ Hj)
{
    long idx = (long)blockIdx.x * 256 + threadIdx.x;
    if (idx >= (long)NROWS * H3) return;
    int r = (int)(idx / H3);
    int c = (int)(idx % H3);
    float v;
    if (c < Hh)          v = g_ctx[(long)r*Hh + c];
    else if (c < 2*Hh)   v = Hj[(long)r*Hh + (c - Hh)];
    else {
        int cc = c - 2*Hh;
        v = g_ctx[(long)r*Hh + cc] * Hj[(long)r*Hh + cc];
    }
    g_msgin[idx] = v;
}

// ============================================================
// K7: split-K reduce + epilogue (vectorized float4)
// ============================================================
template<bool RELU, bool SCALE>
__global__ __launch_bounds__(256) void reduce_kernel(
    const float* __restrict__ p, float* __restrict__ out,
    const float* __restrict__ bias, const float* __restrict__ scale_ptr,
    int N, long total)
{
    long i4 = ((long)blockIdx.x * 256 + threadIdx.x) * 4;
    if (i4 >= total) return;
    int col = (int)(i4 % N);
    float4 a = *(const float4*)&p[i4];
    float4 b = *(const float4*)&p[total + i4];
    float4 bi = *(const float4*)&bias[col];
    float sc = SCALE ? __ldg(scale_ptr) : 1.f;
    float4 o;
    o.x = a.x + b.x + bi.x; o.y = a.y + b.y + bi.y;
    o.z = a.z + b.z + bi.z; o.w = a.w + b.w + bi.w;
    if (RELU){ o.x=fmaxf(o.x,0.f); o.y=fmaxf(o.y,0.f); o.z=fmaxf(o.z,0.f); o.w=fmaxf(o.w,0.f); }
    if (SCALE){ o.x*=sc; o.y*=sc; o.z*=sc; o.w*=sc; }
    *(float4*)&out[i4] = o;
}

// ============================================================
extern "C" void kernel_launch(void* const* d_in, const int* in_sizes, int n_in,
                              void* d_out, int out_size)
{
    const float* Hj   = (const float*)d_in[0];
    const float* Hi   = (const float*)d_in[1];
    const float* mask = (const float*)d_in[2];
    const float* pjw  = (const float*)d_in[3];
    const float* piw  = (const float*)d_in[4];
    const float* sw1  = (const float*)d_in[5];
    const float* sb1  = (const float*)d_in[6];
    const float* sw2  = (const float*)d_in[7];
    const float* sb2  = (const float*)d_in[8];
    const float* vw1  = (const float*)d_in[9];
    const float* vb1  = (const float*)d_in[10];
    const float* vw2  = (const float*)d_in[11];
    const float* vb2  = (const float*)d_in[12];
    const float* alpha= (const float*)d_in[13];
    float* out = (float*)d_out;

    void *pprobs, *pctx, *pmsg, *phid, *pp1, *pp2;
    cudaGetSymbolAddress(&pprobs, g_probs);
    cudaGetSymbolAddress(&pctx,   g_ctx);
    cudaGetSymbolAddress(&pmsg,   g_msgin);
    cudaGetSymbolAddress(&phid,   g_hid2);
    cudaGetSymbolAddress(&pp1,    g_part1);
    cudaGetSymbolAddress(&pp2,    g_part2);

    proj_kernel<<<NROWS, 256>>>(Hj, Hi, pjw, piw, sw1);
    pair_kernel<<<NROWS, 256>>>(sw1, sb1, sw2, sb2, mask);

    // ctx_b = probs_b (SxS) @ Hi_b (SxH)   [NN, batched over b]
    {
        dim3 g(Hh/128, Ss/128, Bb);
        gemm2_kernel<false,false,0><<<g, 256>>>(
            (const float*)pprobs, Hi, (float*)pctx, Hh, Ss, Hh, Ss,
            (long)Ss*Ss, (long)Ss*Hh, (long)Ss*Hh, nullptr, nullptr);
    }

    msgin_kernel<<<(int)(((long)NROWS*H3 + 255)/256), 256>>>(Hj);

    // part1 = msg_in @ v_w1^T   [NT, split-K=2]
    {
        dim3 g(OH/128, NROWS/128, 2);
        gemm2_kernel<true,true,0><<<g, 256>>>(
            (const float*)pmsg, vw1, (float*)pp1, OH, H3, H3, H3/2,
            0, 0, (long)NROWS*OH, nullptr, nullptr);
    }
    // hid2 = relu(part1_0 + part1_1 + v_b1)
    {
        long total = (long)NROWS*OH;
        reduce_kernel<true,false><<<(int)((total/4 + 255)/256), 256>>>(
            (const float*)pp1, (float*)phid, vb1, nullptr, OH, total);
    }

    // part2 = hid2 @ v_w2^T   [NT, split-K=2]
    {
        dim3 g(Hh/128, NROWS/128, 2);
        gemm2_kernel<true,true,0><<<g, 256>>>(
            (const float*)phid, vw2, (float*)pp2, Hh, OH, OH, OH/2,
            0, 0, (long)NROWS*Hh, nullptr, nullptr);
    }
    // out = alpha * (part2_0 + part2_1 + v_b2)
    {
        long total = (long)NROWS*Hh;
        reduce_kernel<false,true><<<(int)((total/4 + 255)/256), 256>>>(
            (const float*)pp2, out, vb2, alpha, Hh, total);
    }
    (void)in_sizes; (void)n_in; (void)out_size;
}